// round 2
// baseline (speedup 1.0000x reference)
#include <cuda_runtime.h>
#include <cuda_bf16.h>

// Shapes fixed by problem: T=1024, B=8, D=64, N=64
#define T_DIM 1024
#define B_DIM 8
#define CH    32                   // chunks over T
#define TC    (T_DIM / CH)         // 32 timesteps per chunk
#define EPSV  1e-8f

// Scratch (device globals, allocation-free)
__device__ float  gLogAgg[CH * B_DIM * 64];     // per-(c,b,n) chunk log-alpha sums
__device__ float4 gC[CH * B_DIM * 1024];        // per-(c,b) chunk outer-product sums (4 MB)
__device__ int    gLogFlag[CH * B_DIM];
__device__ int    gCFlag[CH * B_DIM];

__device__ __forceinline__ int ld_acq(const int* p) {
    int v;
    asm volatile("ld.acquire.gpu.b32 %0, [%1];" : "=r"(v) : "l"(p) : "memory");
    return v;
}
__device__ __forceinline__ void st_rel(int* p, int v) {
    asm volatile("st.release.gpu.b32 [%0], %1;" :: "l"(p), "r"(v) : "memory");
}

// Reset flags every launch (graph replays reuse device globals).
__global__ void k_clear() {
    int i = threadIdx.x;
    if (i < CH * B_DIM) { gLogFlag[i] = 0; gCFlag[i] = 0; }
}

// One block per (chunk c, batch b). 256 blocks, all co-resident on 148 SMs.
__global__ void __launch_bounds__(512)
k_fused(const float* __restrict__ vv,
        const float* __restrict__ kk,
        const float* __restrict__ alpha,
        float4* __restrict__ out) {
    const int c = blockIdx.x, b = blockIdx.y;
    const int tid = threadIdx.x;

    __shared__ float  s_v[TC][64];
    __shared__ float4 s_w4[TC][16];     // log-alpha scan workspace, then w = k*decay
    __shared__ float  s_k[TC][64];
    __shared__ float  s_tot[8][64];
    __shared__ float  s_pre[64], s_inv[64];
    float* s_w = (float*)s_w4;

    // ---- A: coalesced tile loads; log(max(alpha,eps)) on the fly ----
    for (int i = tid; i < TC * 64; i += 512) {
        int t = i >> 6, j = i & 63;
        int g = ((c * TC + t) * B_DIM + b) * 64 + j;
        s_v[t][j]      = vv[g];
        s_k[t][j]      = kk[g];
        s_w[t * 64 + j] = logf(fmaxf(alpha[g], EPSV));
    }
    __syncthreads();

    // ---- B: chunk-local inclusive cumsum over t, per n ----
    const int tq = tid >> 6;     // 0..7, owns 4 timesteps
    const int n  = tid & 63;
    {
        float r = 0.f;
#pragma unroll
        for (int i = 0; i < 4; i++) {
            int t = tq * 4 + i;
            r += s_w[t * 64 + n];
            s_w[t * 64 + n] = r;
        }
        s_tot[tq][n] = r;
    }
    __syncthreads();
    if (tid < 64) {
        float run = 0.f;
#pragma unroll
        for (int q = 0; q < 8; q++) { float x = s_tot[q][tid]; s_tot[q][tid] = run; run += x; }
        gLogAgg[(c * B_DIM + b) * 64 + tid] = run;      // chunk aggregate
        __threadfence();
    }
    __syncthreads();
    if (tid == 0) st_rel(&gLogFlag[c * B_DIM + b], 1);
    {
        float off = s_tot[tq][n];
#pragma unroll
        for (int i = 0; i < 4; i++) s_w[(tq * 4 + i) * 64 + n] += off;
    }

    // ---- C: wait for ALL chunk log-aggregates of this batch (need total for normalizer) ----
    if (tid < CH) {
        while (ld_acq(&gLogFlag[tid * B_DIM + b]) == 0) __nanosleep(40);
    }
    __syncthreads();
    if (tid < 64) {
        float pre = 0.f, tot = 0.f;
#pragma unroll
        for (int cc = 0; cc < CH; cc++) {
            float a = __ldcg(&gLogAgg[(cc * B_DIM + b) * 64 + tid]);
            tot += a;
            if (cc < c) pre += a;
        }
        s_pre[tid] = pre;
        s_inv[tid] = 1.f / (expf(tot) + EPSV);
    }
    __syncthreads();

    // ---- D: w[t][n] = k * exp(logc) / (exp(total)+eps)  (same math as R1) ----
    {
        float pre = s_pre[n], inv = s_inv[n];
#pragma unroll
        for (int i = 0; i < 4; i++) {
            int t = tq * 4 + i;
            s_w[t * 64 + n] = s_k[t][n] * expf(s_w[t * 64 + n] + pre) * inv;
        }
    }
    __syncthreads();

    // ---- E: chunk outer-product sum C_c  (thread owns (d, n4) and (d+32, n4)) ----
    const int d  = tid >> 4;     // 0..31
    const int n4 = tid & 15;
    float4 a0 = make_float4(0.f, 0.f, 0.f, 0.f), a1 = a0;
#pragma unroll
    for (int t = 0; t < TC; t++) {
        float v0 = s_v[t][d], v1 = s_v[t][d + 32];
        float4 w = s_w4[t][n4];
        a0.x += v0 * w.x; a0.y += v0 * w.y; a0.z += v0 * w.z; a0.w += v0 * w.w;
        a1.x += v1 * w.x; a1.y += v1 * w.y; a1.z += v1 * w.z; a1.w += v1 * w.w;
    }
    {
        int base = (c * B_DIM + b) * 1024;
        gC[base + d * 16 + n4]        = a0;
        gC[base + (d + 32) * 16 + n4] = a1;
    }
    __threadfence();
    __syncthreads();
    if (tid == 0) st_rel(&gCFlag[c * B_DIM + b], 1);

    // ---- F: lookback — sum predecessor chunk tiles straight from L2 ----
    if (tid < c) {
        while (ld_acq(&gCFlag[tid * B_DIM + b]) == 0) __nanosleep(40);
    }
    __syncthreads();
    float4 p0 = make_float4(0.f, 0.f, 0.f, 0.f), p1 = p0;
    for (int cc = 0; cc < c; cc++) {
        int base = (cc * B_DIM + b) * 1024;
        float4 x0 = __ldcg(&gC[base + d * 16 + n4]);
        float4 x1 = __ldcg(&gC[base + (d + 32) * 16 + n4]);
        p0.x += x0.x; p0.y += x0.y; p0.z += x0.z; p0.w += x0.w;
        p1.x += x1.x; p1.y += x1.y; p1.z += x1.z; p1.w += x1.w;
    }

    // ---- G: final pass — running accum from prefix, stream 134 MB out ----
#pragma unroll
    for (int t = 0; t < TC; t++) {
        float v0 = s_v[t][d], v1 = s_v[t][d + 32];
        float4 w = s_w4[t][n4];
        p0.x += v0 * w.x; p0.y += v0 * w.y; p0.z += v0 * w.z; p0.w += v0 * w.w;
        p1.x += v1 * w.x; p1.y += v1 * w.y; p1.z += v1 * w.z; p1.w += v1 * w.w;
        int o = ((c * TC + t) * B_DIM + b) * 1024;
        out[o + d * 16 + n4]        = p0;
        out[o + (d + 32) * 16 + n4] = p1;
    }
}

// ---------------------------------------------------------------------------
extern "C" void kernel_launch(void* const* d_in, const int* in_sizes, int n_in,
                              void* d_out, int out_size) {
    (void)in_sizes; (void)n_in; (void)out_size;
    const float* v     = (const float*)d_in[0];
    const float* k     = (const float*)d_in[1];
    const float* alpha = (const float*)d_in[2];
    float4* out = (float4*)d_out;

    k_clear<<<1, 256>>>();
    k_fused<<<dim3(CH, B_DIM), 512>>>(v, k, alpha, out);
}

// round 3
// speedup vs baseline: 1.0661x; 1.0661x over previous
#include <cuda_runtime.h>
#include <cuda_bf16.h>

// Shapes fixed by problem: T=1024, B=8, D=64, N=64
#define T_DIM 1024
#define B_DIM 8
#define BN    (B_DIM * 64)         // 512
#define CH    32                   // chunks over T
#define TC    (T_DIM / CH)         // 32 timesteps per chunk
#define EPSV  1e-8f

// Scratch (device globals, allocation-free)
__device__ float  gLocal[T_DIM * BN];        // chunk-local inclusive log-cumsum (2 MB)
__device__ float  gLogAgg[CH * B_DIM * 64];  // per-(c,b,n) chunk log sums
__device__ float  gPre[CH * B_DIM * 64];     // exclusive chunk prefix of log sums
__device__ float  gInv[B_DIM * 64];          // 1/(exp(total)+eps)
__device__ float  gW[T_DIM * BN];            // w = k * decay (2 MB)
__device__ float4 gC[CH * B_DIM * 1024];     // chunk outer-product sums (4 MB)
__device__ float4 gP[CH * B_DIM * 1024];     // exclusive prefix of gC (4 MB)

// ---------------------------------------------------------------------------
// K1: per (c,b): chunk-local inclusive cumsum of log(max(alpha,eps)) over t.
// Coalesced loads/stores. grid (CH,B), 256 threads.
// ---------------------------------------------------------------------------
__global__ void __launch_bounds__(256)
k_chunkscan(const float* __restrict__ alpha) {
    const int c = blockIdx.x, b = blockIdx.y;
    const int tid = threadIdx.x;

    __shared__ float s[TC][64];
    __shared__ float s_tot[4][64];

    for (int i = tid; i < TC * 64; i += 256) {
        int t = i >> 6, j = i & 63;
        s[t][j] = logf(fmaxf(alpha[((c * TC + t) * B_DIM + b) * 64 + j], EPSV));
    }
    __syncthreads();

    const int tq = tid >> 6;     // 0..3, owns 8 timesteps
    const int n  = tid & 63;
    {
        float r = 0.f;
#pragma unroll
        for (int i = 0; i < 8; i++) {
            int t = tq * 8 + i;
            r += s[t][n];
            s[t][n] = r;
        }
        s_tot[tq][n] = r;
    }
    __syncthreads();
    if (tid < 64) {
        float run = 0.f;
#pragma unroll
        for (int q = 0; q < 4; q++) { float x = s_tot[q][tid]; s_tot[q][tid] = run; run += x; }
        gLogAgg[(c * B_DIM + b) * 64 + tid] = run;
    }
    __syncthreads();
    {
        float off = s_tot[tq][n];
#pragma unroll
        for (int i = 0; i < 8; i++) {
            int t = tq * 8 + i;
            gLocal[((c * TC + t) * B_DIM + b) * 64 + n] = s[t][n] + off;
        }
    }
}

// ---------------------------------------------------------------------------
// K2: scan chunk aggregates -> exclusive prefixes + normalizer. grid B, 64 thr.
// ---------------------------------------------------------------------------
__global__ void __launch_bounds__(64)
k_aggscan() {
    const int b = blockIdx.x;
    const int n = threadIdx.x;
    float run = 0.f;
#pragma unroll
    for (int cc = 0; cc < CH; cc++) {
        int idx = (cc * B_DIM + b) * 64 + n;
        float x = gLogAgg[idx];
        gPre[idx] = run;
        run += x;
    }
    gInv[b * 64 + n] = 1.f / (expf(run) + EPSV);
}

// ---------------------------------------------------------------------------
// K3: w = k * exp(local + pre) * inv  -> gW; chunk outer sums -> gC.
// grid (CH,B), 512 threads.
// ---------------------------------------------------------------------------
__global__ void __launch_bounds__(512)
k_wchunk(const float* __restrict__ vv, const float* __restrict__ kk) {
    const int c = blockIdx.x, b = blockIdx.y;
    const int tid = threadIdx.x;

    __shared__ float  s_v[TC][64];
    __shared__ float4 s_w4[TC][16];
    __shared__ float  s_pre[64], s_inv[64];
    float* s_w = (float*)s_w4;

    if (tid < 64) {
        s_pre[tid] = gPre[(c * B_DIM + b) * 64 + tid];
        s_inv[tid] = gInv[b * 64 + tid];
    }
    __syncthreads();

    for (int i = tid; i < TC * 64; i += 512) {
        int t = i >> 6, j = i & 63;
        int g = ((c * TC + t) * B_DIM + b) * 64 + j;
        s_v[t][j] = vv[g];
        float w = kk[g] * expf(gLocal[g] + s_pre[j]) * s_inv[j];
        s_w[t * 64 + j] = w;
        gW[g] = w;
    }
    __syncthreads();

    const int d  = tid >> 4;     // 0..31
    const int n4 = tid & 15;
    float4 a0 = make_float4(0.f, 0.f, 0.f, 0.f), a1 = a0;
#pragma unroll
    for (int t = 0; t < TC; t++) {
        float v0 = s_v[t][d], v1 = s_v[t][d + 32];
        float4 w = s_w4[t][n4];
        a0.x += v0 * w.x; a0.y += v0 * w.y; a0.z += v0 * w.z; a0.w += v0 * w.w;
        a1.x += v1 * w.x; a1.y += v1 * w.y; a1.z += v1 * w.z; a1.w += v1 * w.w;
    }
    int base = (c * B_DIM + b) * 1024;
    gC[base + d * 16 + n4]        = a0;
    gC[base + (d + 32) * 16 + n4] = a1;
}

// ---------------------------------------------------------------------------
// K4: exclusive prefix over chunks of gC, smem-staged & coalesced.
// grid (16 slices, B), 512 threads. Each block: one b, 64 float4 lanes.
// ---------------------------------------------------------------------------
__global__ void __launch_bounds__(512)
k_prefix2() {
    const int s = blockIdx.x;            // 0..15 slice of 64 float4s
    const int b = blockIdx.y;
    const int tid = threadIdx.x;

    __shared__ float4 sm[CH][64];        // 32 KB
    float* smf = (float*)sm;

    for (int i = tid; i < CH * 64; i += 512) {
        int cc = i >> 6, e = i & 63;
        sm[cc][e] = gC[(cc * B_DIM + b) * 1024 + s * 64 + e];
    }
    __syncthreads();

    if (tid < 256) {                     // one float column per thread
        float run = 0.f;
#pragma unroll
        for (int cc = 0; cc < CH; cc++) {
            float x = smf[cc * 256 + tid];
            smf[cc * 256 + tid] = run;
            run += x;
        }
    }
    __syncthreads();

    for (int i = tid; i < CH * 64; i += 512) {
        int cc = i >> 6, e = i & 63;
        gP[(cc * B_DIM + b) * 1024 + s * 64 + e] = sm[cc][e];
    }
}

// ---------------------------------------------------------------------------
// K5: main writer. grid (CH, B, 2): z selects d-half. 512 threads.
// thread = (d = 32*h + tid/16, n4 = tid%16). Streams 134 MB out.
// ---------------------------------------------------------------------------
__global__ void __launch_bounds__(512)
k_main(const float* __restrict__ vv, float4* __restrict__ out) {
    const int c = blockIdx.x, b = blockIdx.y, h = blockIdx.z;
    const int tid = threadIdx.x;

    __shared__ float  s_v[TC][32];
    __shared__ float4 s_w4[TC][16];

    for (int i = tid; i < TC * 32; i += 512) {
        int t = i >> 5, j = i & 31;
        s_v[t][j] = vv[((c * TC + t) * B_DIM + b) * 64 + h * 32 + j];
    }
    for (int i = tid; i < TC * 64; i += 512) {
        int t = i >> 6, j = i & 63;
        ((float*)s_w4)[t * 64 + j] = gW[((c * TC + t) * B_DIM + b) * 64 + j];
    }
    __syncthreads();

    const int dl = tid >> 4;             // 0..31 local d
    const int n4 = tid & 15;
    const int d  = h * 32 + dl;

    float4 acc = gP[(c * B_DIM + b) * 1024 + d * 16 + n4];

#pragma unroll
    for (int t = 0; t < TC; t++) {
        float  vt = s_v[t][dl];
        float4 wt = s_w4[t][n4];
        acc.x += vt * wt.x;
        acc.y += vt * wt.y;
        acc.z += vt * wt.z;
        acc.w += vt * wt.w;
        out[((c * TC + t) * B_DIM + b) * 1024 + d * 16 + n4] = acc;
    }
}

// ---------------------------------------------------------------------------
extern "C" void kernel_launch(void* const* d_in, const int* in_sizes, int n_in,
                              void* d_out, int out_size) {
    (void)in_sizes; (void)n_in; (void)out_size;
    const float* v     = (const float*)d_in[0];
    const float* k     = (const float*)d_in[1];
    const float* alpha = (const float*)d_in[2];
    float4* out = (float4*)d_out;

    k_chunkscan<<<dim3(CH, B_DIM), 256>>>(alpha);
    k_aggscan<<<B_DIM, 64>>>();
    k_wchunk<<<dim3(CH, B_DIM), 512>>>(v, k);
    k_prefix2<<<dim3(16, B_DIM), 512>>>();
    k_main<<<dim3(CH, B_DIM, 2), 512>>>(v, out);
}

// round 4
// speedup vs baseline: 1.1879x; 1.1143x over previous
#include <cuda_runtime.h>
#include <cuda_bf16.h>

// Shapes fixed by problem: T=1024, B=8, D=64, N=64
#define T_DIM 1024
#define B_DIM 8
#define BN    (B_DIM * 64)         // 512
#define CH    32                   // chunks over T
#define TC    (T_DIM / CH)         // 32 timesteps per chunk
#define EPSV  1e-8f

// Scratch (device globals, allocation-free)
__device__ float  gLocal[T_DIM * BN];        // chunk-local inclusive log-cumsum (2 MB)
__device__ float  gLogAgg[CH * B_DIM * 64];  // per-(c,b,n) chunk log sums
__device__ float  gW[T_DIM * BN];            // w = k * decay (2 MB)
__device__ float4 gC[CH * B_DIM * 1024];     // chunk outer-product sums (4 MB)

// ---------------------------------------------------------------------------
// K1: per (c,b): chunk-local inclusive cumsum of log(max(alpha,eps)) over t.
// Coalesced loads/stores. grid (CH,B), 256 threads.
// ---------------------------------------------------------------------------
__global__ void __launch_bounds__(256)
k_chunkscan(const float* __restrict__ alpha) {
    const int c = blockIdx.x, b = blockIdx.y;
    const int tid = threadIdx.x;

    __shared__ float s[TC][64];
    __shared__ float s_tot[4][64];

    for (int i = tid; i < TC * 64; i += 256) {
        int t = i >> 6, j = i & 63;
        s[t][j] = logf(fmaxf(alpha[((c * TC + t) * B_DIM + b) * 64 + j], EPSV));
    }
    __syncthreads();

    const int tq = tid >> 6;     // 0..3, owns 8 timesteps
    const int n  = tid & 63;
    {
        float r = 0.f;
#pragma unroll
        for (int i = 0; i < 8; i++) {
            int t = tq * 8 + i;
            r += s[t][n];
            s[t][n] = r;
        }
        s_tot[tq][n] = r;
    }
    __syncthreads();
    if (tid < 64) {
        float run = 0.f;
#pragma unroll
        for (int q = 0; q < 4; q++) { float x = s_tot[q][tid]; s_tot[q][tid] = run; run += x; }
        gLogAgg[(c * B_DIM + b) * 64 + tid] = run;
    }
    __syncthreads();
    {
        float off = s_tot[tq][n];
#pragma unroll
        for (int i = 0; i < 8; i++) {
            int t = tq * 8 + i;
            gLocal[((c * TC + t) * B_DIM + b) * 64 + n] = s[t][n] + off;
        }
    }
}

// ---------------------------------------------------------------------------
// K2: inline aggregate scan (redundant per block, 8 KB from L2), then
//     w = k * exp(local + pre) * inv  -> gW; chunk outer sums -> gC.
// grid (CH,B), 512 threads.
// ---------------------------------------------------------------------------
__global__ void __launch_bounds__(512)
k_wchunk(const float* __restrict__ vv, const float* __restrict__ kk) {
    const int c = blockIdx.x, b = blockIdx.y;
    const int tid = threadIdx.x;

    __shared__ float  s_v[TC][64];
    __shared__ float4 s_w4[TC][16];
    __shared__ float  s_pre[64], s_inv[64];
    float* s_w = (float*)s_w4;

    // inline scan of chunk log-aggregates for this batch (same order as before)
    if (tid < 64) {
        float run = 0.f, pre = 0.f;
#pragma unroll
        for (int cc = 0; cc < CH; cc++) {
            if (cc == c) pre = run;
            run += __ldg(&gLogAgg[(cc * B_DIM + b) * 64 + tid]);
        }
        s_pre[tid] = pre;
        s_inv[tid] = 1.f / (expf(run) + EPSV);
    }
    __syncthreads();

    for (int i = tid; i < TC * 64; i += 512) {
        int t = i >> 6, j = i & 63;
        int g = ((c * TC + t) * B_DIM + b) * 64 + j;
        s_v[t][j] = vv[g];
        float w = kk[g] * expf(gLocal[g] + s_pre[j]) * s_inv[j];
        s_w[t * 64 + j] = w;
        gW[g] = w;
    }
    __syncthreads();

    const int d  = tid >> 4;     // 0..31
    const int n4 = tid & 15;
    float4 a0 = make_float4(0.f, 0.f, 0.f, 0.f), a1 = a0;
#pragma unroll
    for (int t = 0; t < TC; t++) {
        float v0 = s_v[t][d], v1 = s_v[t][d + 32];
        float4 w = s_w4[t][n4];
        a0.x += v0 * w.x; a0.y += v0 * w.y; a0.z += v0 * w.z; a0.w += v0 * w.w;
        a1.x += v1 * w.x; a1.y += v1 * w.y; a1.z += v1 * w.z; a1.w += v1 * w.w;
    }
    int base = (c * B_DIM + b) * 1024;
    gC[base + d * 16 + n4]        = a0;
    gC[base + (d + 32) * 16 + n4] = a1;
}

// ---------------------------------------------------------------------------
// K3: main writer with inline chunk-prefix lookback.
// grid (CH, B, 2): z selects d-half. 512 threads.
// thread = (d = 32*h + tid/16, n4 = tid%16). Streams 134 MB out.
// ---------------------------------------------------------------------------
__global__ void __launch_bounds__(512)
k_main(const float* __restrict__ vv, float4* __restrict__ out) {
    const int c = blockIdx.x, b = blockIdx.y, h = blockIdx.z;
    const int tid = threadIdx.x;

    __shared__ float  s_v[TC][32];
    __shared__ float4 s_w4[TC][16];

    for (int i = tid; i < TC * 32; i += 512) {
        int t = i >> 5, j = i & 31;
        s_v[t][j] = vv[((c * TC + t) * B_DIM + b) * 64 + h * 32 + j];
    }
    for (int i = tid; i < TC * 64; i += 512) {
        int t = i >> 6, j = i & 63;
        ((float*)s_w4)[t * 64 + j] = gW[((c * TC + t) * B_DIM + b) * 64 + j];
    }

    const int dl = tid >> 4;             // 0..31 local d
    const int n4 = tid & 15;
    const int d  = h * 32 + dl;

    // inline exclusive prefix: sum predecessor chunk tiles from L2 (same order)
    float4 acc = make_float4(0.f, 0.f, 0.f, 0.f);
    const int lane = d * 16 + n4;
    for (int cc = 0; cc < c; cc++) {
        float4 x = __ldg(&gC[(cc * B_DIM + b) * 1024 + lane]);
        acc.x += x.x; acc.y += x.y; acc.z += x.z; acc.w += x.w;
    }
    __syncthreads();

#pragma unroll
    for (int t = 0; t < TC; t++) {
        float  vt = s_v[t][dl];
        float4 wt = s_w4[t][n4];
        acc.x += vt * wt.x;
        acc.y += vt * wt.y;
        acc.z += vt * wt.z;
        acc.w += vt * wt.w;
        out[((c * TC + t) * B_DIM + b) * 1024 + lane] = acc;
    }
}

// ---------------------------------------------------------------------------
extern "C" void kernel_launch(void* const* d_in, const int* in_sizes, int n_in,
                              void* d_out, int out_size) {
    (void)in_sizes; (void)n_in; (void)out_size;
    const float* v     = (const float*)d_in[0];
    const float* k     = (const float*)d_in[1];
    const float* alpha = (const float*)d_in[2];
    float4* out = (float4*)d_out;

    k_chunkscan<<<dim3(CH, B_DIM), 256>>>(alpha);
    k_wchunk<<<dim3(CH, B_DIM), 512>>>(v, k);
    k_main<<<dim3(CH, B_DIM, 2), 512>>>(v, out);
}

// round 5
// speedup vs baseline: 1.2574x; 1.0585x over previous
#include <cuda_runtime.h>
#include <cuda_bf16.h>

// Shapes fixed by problem: T=1024, B=8, D=64, N=64
#define T_DIM 1024
#define B_DIM 8
#define CH    32                   // chunks over T
#define TC    (T_DIM / CH)         // 32 timesteps per chunk
#define EPSV  1e-8f

// Scratch (device globals, allocation-free)
__device__ float  gLogAgg[CH * B_DIM * 64];  // per-(c,b,n) chunk log-alpha sums
__device__ float4 gC[CH * B_DIM * 1024];     // chunk outer-product sums (half tiles interleaved)
__device__ int    gFlag[CH * B_DIM * 2];     // publish flags per (c,b,h)

__device__ __forceinline__ int ld_acq(const int* p) {
    int v;
    asm volatile("ld.acquire.gpu.b32 %0, [%1];" : "=r"(v) : "l"(p) : "memory");
    return v;
}
__device__ __forceinline__ void st_rel(int* p, int v) {
    asm volatile("st.release.gpu.b32 [%0], %1;" :: "l"(p), "r"(v) : "memory");
}

// ---------------------------------------------------------------------------
// K1: chunk log-aggregates only: gLogAgg[c,b,n] = sum_t log(max(alpha,eps)).
// Also clears this (c,b)'s flags for the following kernel (graph replays).
// grid (CH,B), 256 threads.
// ---------------------------------------------------------------------------
__global__ void __launch_bounds__(256)
k_agg(const float* __restrict__ alpha) {
    const int c = blockIdx.x, b = blockIdx.y;
    const int tid = threadIdx.x;

    if (tid < 2) gFlag[(c * B_DIM + b) * 2 + tid] = 0;

    __shared__ float s_tot[4][64];

    const int tq = tid >> 6;     // 0..3, owns 8 timesteps
    const int n  = tid & 63;
    float r = 0.f;
#pragma unroll
    for (int i = 0; i < 8; i++) {
        int t = tq * 8 + i;
        r += logf(fmaxf(alpha[((c * TC + t) * B_DIM + b) * 64 + n], EPSV));
    }
    s_tot[tq][n] = r;
    __syncthreads();
    if (tid < 64) {
        gLogAgg[(c * B_DIM + b) * 64 + tid] =
            s_tot[0][tid] + s_tot[1][tid] + s_tot[2][tid] + s_tot[3][tid];
    }
}

// ---------------------------------------------------------------------------
// K2: everything else, one launch. grid (CH, B, 2) = 512 blocks, 512 threads.
// Block (c,b,h): h selects d-half (rows h*32..h*32+31).
// ---------------------------------------------------------------------------
__global__ void __launch_bounds__(512)
k_fused2(const float* __restrict__ vv,
         const float* __restrict__ kk,
         const float* __restrict__ alpha,
         float4* __restrict__ out) {
    const int c = blockIdx.x, b = blockIdx.y, h = blockIdx.z;
    const int tid = threadIdx.x;

    __shared__ float  s_v[TC][32];
    __shared__ float4 s_w4[TC][16];
    __shared__ float  s_pre[64], s_inv[64];
    float* s_w = (float*)s_w4;

    // ---- Phase 0: pre/inv from chunk aggregates (cross-kernel dependency) ----
    if (tid < 64) {
        float run = 0.f, pre = 0.f;
#pragma unroll
        for (int cc = 0; cc < CH; cc++) {
            if (cc == c) pre = run;
            run += __ldg(&gLogAgg[(cc * B_DIM + b) * 64 + tid]);
        }
        s_pre[tid] = pre;
        s_inv[tid] = 1.f / (expf(run) + EPSV);
    }

    // ---- Phase 1a: load v half + alpha/k -> logs into s_w ----
    for (int i = tid; i < TC * 32; i += 512) {
        int t = i >> 5, j = i & 31;
        s_v[t][j] = vv[((c * TC + t) * B_DIM + b) * 64 + h * 32 + j];
    }
    for (int i = tid; i < TC * 64; i += 512) {
        int t = i >> 6, j = i & 63;
        int g = ((c * TC + t) * B_DIM + b) * 64 + j;
        s_w[t * 64 + j] = logf(fmaxf(alpha[g], EPSV));
    }
    __syncthreads();

    // ---- Phase 1b: chunk-local inclusive scan over t, then w = k*exp(.)*inv ----
    const int tq = tid >> 6;     // 0..7, owns 4 timesteps
    const int n  = tid & 63;
    __shared__ float s_tot[8][64];
    {
        float r = 0.f;
#pragma unroll
        for (int i = 0; i < 4; i++) {
            int t = tq * 4 + i;
            r += s_w[t * 64 + n];
            s_w[t * 64 + n] = r;
        }
        s_tot[tq][n] = r;
    }
    __syncthreads();
    if (tid < 64) {
        float run = 0.f;
#pragma unroll
        for (int q = 0; q < 8; q++) { float x = s_tot[q][tid]; s_tot[q][tid] = run; run += x; }
    }
    __syncthreads();
    {
        float off = s_tot[tq][n] + s_pre[n];
        float inv = s_inv[n];
#pragma unroll
        for (int i = 0; i < 4; i++) {
            int t = tq * 4 + i;
            int g = ((c * TC + t) * B_DIM + b) * 64 + n;
            s_w[t * 64 + n] = kk[g] * expf(s_w[t * 64 + n] + off) * inv;
        }
    }
    __syncthreads();

    // ---- Phase 2: half-d chunk outer sum -> gC, publish ----
    const int dl = tid >> 4;     // 0..31 local d row
    const int n4 = tid & 15;
    const int lane = (h * 32 + dl) * 16 + n4;
    {
        float4 a = make_float4(0.f, 0.f, 0.f, 0.f);
#pragma unroll
        for (int t = 0; t < TC; t++) {
            float  v0 = s_v[t][dl];
            float4 w  = s_w4[t][n4];
            a.x += v0 * w.x; a.y += v0 * w.y; a.z += v0 * w.z; a.w += v0 * w.w;
        }
        gC[(c * B_DIM + b) * 1024 + lane] = a;
    }
    __threadfence();
    __syncthreads();
    if (tid == 0) st_rel(&gFlag[(c * B_DIM + b) * 2 + h], 1);

    // ---- Phase 3: forward lookback over predecessors (cc < c) ----
    if (tid < c) {
        while (ld_acq(&gFlag[(tid * B_DIM + b) * 2 + h]) == 0) __nanosleep(20);
    }
    __syncthreads();
    float4 acc = make_float4(0.f, 0.f, 0.f, 0.f);
    for (int cc = 0; cc < c; cc++) {
        float4 x = __ldcg(&gC[(cc * B_DIM + b) * 1024 + lane]);
        acc.x += x.x; acc.y += x.y; acc.z += x.z; acc.w += x.w;
    }

    // ---- Phase 4: stream the output ----
#pragma unroll
    for (int t = 0; t < TC; t++) {
        float  vt = s_v[t][dl];
        float4 wt = s_w4[t][n4];
        acc.x += vt * wt.x;
        acc.y += vt * wt.y;
        acc.z += vt * wt.z;
        acc.w += vt * wt.w;
        out[((c * TC + t) * B_DIM + b) * 1024 + lane] = acc;
    }
}

// ---------------------------------------------------------------------------
extern "C" void kernel_launch(void* const* d_in, const int* in_sizes, int n_in,
                              void* d_out, int out_size) {
    (void)in_sizes; (void)n_in; (void)out_size;
    const float* v     = (const float*)d_in[0];
    const float* k     = (const float*)d_in[1];
    const float* alpha = (const float*)d_in[2];
    float4* out = (float4*)d_out;

    k_agg<<<dim3(CH, B_DIM), 256>>>(alpha);
    k_fused2<<<dim3(CH, B_DIM, 2), 512>>>(v, k, alpha, out);
}

// round 6
// speedup vs baseline: 1.3757x; 1.0941x over previous
#include <cuda_runtime.h>
#include <cuda_bf16.h>

// Shapes fixed by problem: T=1024, B=8, D=64, N=64
#define T_DIM 1024
#define B_DIM 8
#define CH    32                   // chunks over T
#define TC    (T_DIM / CH)         // 32 timesteps per chunk
#define EPSV  1e-8f

// Scratch (device globals, allocation-free)
__device__ float  gLogAgg[CH * B_DIM * 64];  // log of per-chunk alpha product
__device__ float4 gC[CH * B_DIM * 1024];     // chunk outer-product sums
__device__ int    gFlag[CH * B_DIM * 2];     // publish flags per (c,b,h)

__device__ __forceinline__ int ld_acq(const int* p) {
    int v;
    asm volatile("ld.acquire.gpu.b32 %0, [%1];" : "=r"(v) : "l"(p) : "memory");
    return v;
}
__device__ __forceinline__ void st_rel(int* p, int v) {
    asm volatile("st.release.gpu.b32 [%0], %1;" :: "l"(p), "r"(v) : "memory");
}

// ---------------------------------------------------------------------------
// K1: gLogAgg[c,b,n] = log( prod_t max(alpha,eps) ).  One logf per n.
// Also clears this (c,b)'s flags (graph replays). grid (CH,B), 256 threads.
// ---------------------------------------------------------------------------
__global__ void __launch_bounds__(256)
k_agg(const float* __restrict__ alpha) {
    const int c = blockIdx.x, b = blockIdx.y;
    const int tid = threadIdx.x;

    if (tid < 2) gFlag[(c * B_DIM + b) * 2 + tid] = 0;

    __shared__ float s_tot[4][64];

    const int tq = tid >> 6;     // 0..3, owns 8 timesteps
    const int n  = tid & 63;
    float r = 1.f;
#pragma unroll
    for (int i = 0; i < 8; i++) {
        int t = tq * 8 + i;
        r *= fmaxf(alpha[((c * TC + t) * B_DIM + b) * 64 + n], EPSV);
    }
    s_tot[tq][n] = r;
    __syncthreads();
    if (tid < 64) {
        gLogAgg[(c * B_DIM + b) * 64 + tid] =
            logf(s_tot[0][tid] * s_tot[1][tid] * s_tot[2][tid] * s_tot[3][tid]);
    }
}

// ---------------------------------------------------------------------------
// K2: everything else. grid (CH, B, 2) = 512 blocks, 512 threads.
// Block (c,b,h): h selects d-half. Multiply-scan (no per-element exp/log).
// ---------------------------------------------------------------------------
__global__ void __launch_bounds__(512)
k_fused2(const float* __restrict__ vv,
         const float* __restrict__ kk,
         const float* __restrict__ alpha,
         float4* __restrict__ out) {
    const int c = blockIdx.x, b = blockIdx.y, h = blockIdx.z;
    const int tid = threadIdx.x;

    __shared__ float  s_v[TC][32];
    __shared__ float4 s_w4[TC][16];
    __shared__ float  s_scale[64];
    __shared__ float  s_tot[8][64];
    float* s_w = (float*)s_w4;

    // ---- Phase 0: scale[n] = exp(pre)/(exp(total)+eps)  (2 expf per n) ----
    if (tid < 64) {
        float run = 0.f, pre = 0.f;
#pragma unroll
        for (int cc = 0; cc < CH; cc++) {
            if (cc == c) pre = run;
            run += __ldg(&gLogAgg[(cc * B_DIM + b) * 64 + tid]);
        }
        s_scale[tid] = expf(pre) / (expf(run) + EPSV);
    }

    // ---- Phase 1a: v half-tile load ----
    for (int i = tid; i < TC * 32; i += 512) {
        int t = i >> 5, j = i & 31;
        s_v[t][j] = vv[((c * TC + t) * B_DIM + b) * 64 + h * 32 + j];
    }

    // ---- Phase 1b: chunk-local multiply-scan of clamped alpha (registers) ----
    const int tq = tid >> 6;     // 0..7, owns 4 consecutive timesteps
    const int n  = tid & 63;
    const int gbase = ((c * TC + tq * 4) * B_DIM + b) * 64 + n;  // +512 per t
    float p0, p1, p2, p3;
    {
        float r = fmaxf(alpha[gbase        ], EPSV); p0 = r;
        r      *= fmaxf(alpha[gbase +  512 ], EPSV); p1 = r;
        r      *= fmaxf(alpha[gbase + 1024 ], EPSV); p2 = r;
        r      *= fmaxf(alpha[gbase + 1536 ], EPSV); p3 = r;
        s_tot[tq][n] = r;
    }
    __syncthreads();
    if (tid < 64) {                      // exclusive product across the 8 groups
        float run = 1.f;
#pragma unroll
        for (int q = 0; q < 8; q++) { float x = s_tot[q][tid]; s_tot[q][tid] = run; run *= x; }
    }
    __syncthreads();
    {
        float off = s_tot[tq][n] * s_scale[n];   // group prefix * decay scale
        s_w[(tq * 4 + 0) * 64 + n] = kk[gbase        ] * (p0 * off);
        s_w[(tq * 4 + 1) * 64 + n] = kk[gbase +  512 ] * (p1 * off);
        s_w[(tq * 4 + 2) * 64 + n] = kk[gbase + 1024 ] * (p2 * off);
        s_w[(tq * 4 + 3) * 64 + n] = kk[gbase + 1536 ] * (p3 * off);
    }
    __syncthreads();

    // ---- Phase 2: half-d chunk outer sum -> gC, publish ----
    const int dl = tid >> 4;     // 0..31 local d row
    const int n4 = tid & 15;
    const int lane = (h * 32 + dl) * 16 + n4;
    {
        float4 a = make_float4(0.f, 0.f, 0.f, 0.f);
#pragma unroll
        for (int t = 0; t < TC; t++) {
            float  v0 = s_v[t][dl];
            float4 w  = s_w4[t][n4];
            a.x += v0 * w.x; a.y += v0 * w.y; a.z += v0 * w.z; a.w += v0 * w.w;
        }
        gC[(c * B_DIM + b) * 1024 + lane] = a;
    }
    __syncthreads();
    if (tid == 0) st_rel(&gFlag[(c * B_DIM + b) * 2 + h], 1);

    // ---- Phase 3: forward lookback over predecessors (cc < c) ----
    if (tid < c) {
        while (ld_acq(&gFlag[(tid * B_DIM + b) * 2 + h]) == 0) __nanosleep(20);
    }
    __syncthreads();
    float4 acc = make_float4(0.f, 0.f, 0.f, 0.f);
    for (int cc = 0; cc < c; cc++) {
        float4 x = __ldcg(&gC[(cc * B_DIM + b) * 1024 + lane]);
        acc.x += x.x; acc.y += x.y; acc.z += x.z; acc.w += x.w;
    }

    // ---- Phase 4: stream the 134 MB output ----
#pragma unroll
    for (int t = 0; t < TC; t++) {
        float  vt = s_v[t][dl];
        float4 wt = s_w4[t][n4];
        acc.x += vt * wt.x;
        acc.y += vt * wt.y;
        acc.z += vt * wt.z;
        acc.w += vt * wt.w;
        out[((c * TC + t) * B_DIM + b) * 1024 + lane] = acc;
    }
}

// ---------------------------------------------------------------------------
extern "C" void kernel_launch(void* const* d_in, const int* in_sizes, int n_in,
                              void* d_out, int out_size) {
    (void)in_sizes; (void)n_in; (void)out_size;
    const float* v     = (const float*)d_in[0];
    const float* k     = (const float*)d_in[1];
    const float* alpha = (const float*)d_in[2];
    float4* out = (float4*)d_out;

    k_agg<<<dim3(CH, B_DIM), 256>>>(alpha);
    k_fused2<<<dim3(CH, B_DIM, 2), 512>>>(v, k, alpha, out);
}